// round 14
// baseline (speedup 1.0000x reference)
#include <cuda_runtime.h>
#include <cstdint>

// ROI pooling (TF1 bilinear resize, align_corners=False)
// img:  (1, 1024, 1024, 128) fp32 NHWC
// rois: (1, 512, 4) fp32 = (x1, y1, w, h), integral values
// out:  (1, 512, 7, 7, 128) fp32
//
// FINAL (R6 design; re-confirmed R12, R13). One warp per output pixel; each
// bilinear tap is a contiguous 512 B channel vector -> lane l loads float4
// at channel 4l. Zero-weight tap skip: fx==0 (px==0, or w%7==0 for the
// whole ROI) makes v01/v11 dead weight-zero operands, fy==0 likewise kills
// v10/v11; skipping those loads is bit-exact (v*1 + u*0 == v for finite
// fp32) and cuts read traffic ~25% (ncu-verified: 48 MB -> 36 MB, the
// compulsory floor). __stcs evict-first stores keep the write-once output
// out of L2's way.
//
// Exhausted levers (R1-R13): 2 px/warp MLP boost (timed +0.6us), L2
// evict_last policy (+0.8us cold), 128-thread CTAs (flat), persistent
// single-wave grid (+0.4us cold). Analytically rejected: LDG.256 (issue not
// binding; L1 wavefronts scale with lines, unchanged), half-warp pixel
// pairing (divergence vs traffic tradeoff), ROI-row scheduling (intra-CTA
// x-locality already optimal; ceiling is cross-ROI random-y). Timed metric
// sits at a ~10.3us +/- 0.2us harness floor across all designs (replays run
// L2-warm); cold time ~11.1us is the DRAM random-512B-gather efficiency
// ceiling (~41% of spec) at compulsory traffic.

#define POOL 7
#define NUM_ROIS 512
#define IMG_H 1024
#define IMG_W 1024
#define CH 128

__global__ __launch_bounds__(256) void roi_pool_kernel(
    const float* __restrict__ img,
    const float* __restrict__ rois,
    float* __restrict__ out)
{
    const int warpInBlock = threadIdx.x >> 5;
    const int lane        = threadIdx.x & 31;
    const int pid = blockIdx.x * (blockDim.x >> 5) + warpInBlock; // pixel id
    if (pid >= NUM_ROIS * POOL * POOL) return;

    const int roi = pid / (POOL * POOL);
    const int pix = pid - roi * (POOL * POOL);
    const int py  = pix / POOL;
    const int px  = pix - py * POOL;

    const float4 r = *reinterpret_cast<const float4*>(rois + roi * 4);
    const int x1 = (int)r.x;
    const int y1 = (int)r.y;
    const int w  = (int)r.z;
    const int h  = (int)r.w;

    // TF1 resize: src = dst * (size / POOL), fp32 exactly like the reference
    const float srcy = (float)py * ((float)h / 7.0f);
    const float srcx = (float)px * ((float)w / 7.0f);

    int ylo = (int)floorf(srcy);
    ylo = min(max(ylo, 0), h - 1);
    const float fy = srcy - (float)ylo;
    const int yhi = min(ylo + 1, h - 1);

    int xlo = (int)floorf(srcx);
    xlo = min(max(xlo, 0), w - 1);
    const float fx = srcx - (float)xlo;
    const int xhi = min(xlo + 1, w - 1);

    const int yloA = min(max(y1 + ylo, 0), IMG_H - 1);
    const int yhiA = min(max(y1 + yhi, 0), IMG_H - 1);
    const int xloA = min(max(x1 + xlo, 0), IMG_W - 1);
    const int xhiA = min(max(x1 + xhi, 0), IMG_W - 1);

    // Zero-weight skip flags (warp-uniform; exact-zero test is intentional).
    const bool needX = (fx != 0.0f);
    const bool needY = (fy != 0.0f);

    const float4* p00 = reinterpret_cast<const float4*>(
        img + ((size_t)yloA * IMG_W + xloA) * CH) + lane;
    const float4* p01 = reinterpret_cast<const float4*>(
        img + ((size_t)yloA * IMG_W + xhiA) * CH) + lane;
    const float4* p10 = reinterpret_cast<const float4*>(
        img + ((size_t)yhiA * IMG_W + xloA) * CH) + lane;
    const float4* p11 = reinterpret_cast<const float4*>(
        img + ((size_t)yhiA * IMG_W + xhiA) * CH) + lane;

    // Always need v00. Issue all needed loads back-to-back before consuming.
    const float4 v00 = __ldg(p00);
    float4 v01, v10, v11;
    if (needX)          v01 = __ldg(p01);
    if (needY)          v10 = __ldg(p10);
    if (needX && needY) v11 = __ldg(p11);

    const float gx = 1.0f - fx;
    const float gy = 1.0f - fy;

    float4 o;
    if (needX && needY) {
        float top, bot;
        top = v00.x * gx + v01.x * fx;  bot = v10.x * gx + v11.x * fx;  o.x = top * gy + bot * fy;
        top = v00.y * gx + v01.y * fx;  bot = v10.y * gx + v11.y * fx;  o.y = top * gy + bot * fy;
        top = v00.z * gx + v01.z * fx;  bot = v10.z * gx + v11.z * fx;  o.z = top * gy + bot * fy;
        top = v00.w * gx + v01.w * fx;  bot = v10.w * gx + v11.w * fx;  o.w = top * gy + bot * fy;
    } else if (needX) {
        // fy == 0: out = top exactly (top*1 + bot*0)
        o.x = v00.x * gx + v01.x * fx;
        o.y = v00.y * gx + v01.y * fx;
        o.z = v00.z * gx + v01.z * fx;
        o.w = v00.w * gx + v01.w * fx;
    } else if (needY) {
        // fx == 0: top = v00, bot = v10 exactly
        o.x = v00.x * gy + v10.x * fy;
        o.y = v00.y * gy + v10.y * fy;
        o.z = v00.z * gy + v10.z * fy;
        o.w = v00.w * gy + v10.w * fy;
    } else {
        // fx == fy == 0: out = v00 exactly
        o = v00;
    }

    float4* dst = reinterpret_cast<float4*>(out + (size_t)pid * CH) + lane;
    __stcs(dst, o);
}

extern "C" void kernel_launch(void* const* d_in, const int* in_sizes, int n_in,
                              void* d_out, int out_size)
{
    const float* img  = (const float*)d_in[0];
    const float* rois = (const float*)d_in[1];
    float* out = (float*)d_out;

    const int totalPixels = NUM_ROIS * POOL * POOL;  // 25088
    const int threads = 256;                         // 8 warps = 8 pixels/block
    const int warpsPerBlock = threads / 32;
    const int blocks = (totalPixels + warpsPerBlock - 1) / warpsPerBlock;

    roi_pool_kernel<<<blocks, threads>>>(img, rois, out);
}

// round 15
// speedup vs baseline: 1.0063x; 1.0063x over previous
#include <cuda_runtime.h>
#include <cstdint>

// ROI pooling (TF1 bilinear resize, align_corners=False)
// img:  (1, 1024, 1024, 128) fp32 NHWC
// rois: (1, 512, 4) fp32 = (x1, y1, w, h), integral values
// out:  (1, 512, 7, 7, 128) fp32
//
// FINAL (R6 design; confirmed stationary across R12-R14). One warp per
// output pixel; each bilinear tap is a contiguous 512 B channel vector ->
// lane l loads float4 at channel 4l. Zero-weight tap skip: fx==0 (px==0,
// or w%7==0 for the whole ROI) makes v01/v11 dead weight-zero operands,
// fy==0 likewise kills v10/v11; skipping those loads is bit-exact
// (v*1 + u*0 == v for finite fp32) and cuts read traffic ~25%
// (ncu-verified: 48 MB -> 36 MB, the compulsory floor). __stcs evict-first
// stores keep the write-once output out of L2's way.
//
// Exhausted levers (R1-R14): 2 px/warp MLP boost (timed +0.6us), L2
// evict_last policy (+0.8us cold), 128-thread CTAs (flat), persistent
// single-wave grid (+0.4us cold). Analytically rejected: LDG.256 (issue not
// binding; L1 wavefronts scale with lines, unchanged), tap-pair fused loads
// (same bytes moved), cross-pixel tap sharing (scale>=16/7 => taps disjoint),
// half-warp pixel pairing (divergence vs traffic), ROI-row scheduling
// (intra-CTA x-locality already optimal). Timed metric sits at a ~10.3us
// +/- 0.2us harness floor across all designs (replays run L2-warm); cold
// time ~11.0us is the DRAM random-512B-gather efficiency ceiling (~41% of
// spec) at compulsory traffic.

#define POOL 7
#define NUM_ROIS 512
#define IMG_H 1024
#define IMG_W 1024
#define CH 128

__global__ __launch_bounds__(256) void roi_pool_kernel(
    const float* __restrict__ img,
    const float* __restrict__ rois,
    float* __restrict__ out)
{
    const int warpInBlock = threadIdx.x >> 5;
    const int lane        = threadIdx.x & 31;
    const int pid = blockIdx.x * (blockDim.x >> 5) + warpInBlock; // pixel id
    if (pid >= NUM_ROIS * POOL * POOL) return;

    const int roi = pid / (POOL * POOL);
    const int pix = pid - roi * (POOL * POOL);
    const int py  = pix / POOL;
    const int px  = pix - py * POOL;

    const float4 r = *reinterpret_cast<const float4*>(rois + roi * 4);
    const int x1 = (int)r.x;
    const int y1 = (int)r.y;
    const int w  = (int)r.z;
    const int h  = (int)r.w;

    // TF1 resize: src = dst * (size / POOL), fp32 exactly like the reference
    const float srcy = (float)py * ((float)h / 7.0f);
    const float srcx = (float)px * ((float)w / 7.0f);

    int ylo = (int)floorf(srcy);
    ylo = min(max(ylo, 0), h - 1);
    const float fy = srcy - (float)ylo;
    const int yhi = min(ylo + 1, h - 1);

    int xlo = (int)floorf(srcx);
    xlo = min(max(xlo, 0), w - 1);
    const float fx = srcx - (float)xlo;
    const int xhi = min(xlo + 1, w - 1);

    const int yloA = min(max(y1 + ylo, 0), IMG_H - 1);
    const int yhiA = min(max(y1 + yhi, 0), IMG_H - 1);
    const int xloA = min(max(x1 + xlo, 0), IMG_W - 1);
    const int xhiA = min(max(x1 + xhi, 0), IMG_W - 1);

    // Zero-weight skip flags (warp-uniform; exact-zero test is intentional).
    const bool needX = (fx != 0.0f);
    const bool needY = (fy != 0.0f);

    const float4* p00 = reinterpret_cast<const float4*>(
        img + ((size_t)yloA * IMG_W + xloA) * CH) + lane;
    const float4* p01 = reinterpret_cast<const float4*>(
        img + ((size_t)yloA * IMG_W + xhiA) * CH) + lane;
    const float4* p10 = reinterpret_cast<const float4*>(
        img + ((size_t)yhiA * IMG_W + xloA) * CH) + lane;
    const float4* p11 = reinterpret_cast<const float4*>(
        img + ((size_t)yhiA * IMG_W + xhiA) * CH) + lane;

    // Always need v00. Issue all needed loads back-to-back before consuming.
    const float4 v00 = __ldg(p00);
    float4 v01, v10, v11;
    if (needX)          v01 = __ldg(p01);
    if (needY)          v10 = __ldg(p10);
    if (needX && needY) v11 = __ldg(p11);

    const float gx = 1.0f - fx;
    const float gy = 1.0f - fy;

    float4 o;
    if (needX && needY) {
        float top, bot;
        top = v00.x * gx + v01.x * fx;  bot = v10.x * gx + v11.x * fx;  o.x = top * gy + bot * fy;
        top = v00.y * gx + v01.y * fx;  bot = v10.y * gx + v11.y * fx;  o.y = top * gy + bot * fy;
        top = v00.z * gx + v01.z * fx;  bot = v10.z * gx + v11.z * fx;  o.z = top * gy + bot * fy;
        top = v00.w * gx + v01.w * fx;  bot = v10.w * gx + v11.w * fx;  o.w = top * gy + bot * fy;
    } else if (needX) {
        // fy == 0: out = top exactly (top*1 + bot*0)
        o.x = v00.x * gx + v01.x * fx;
        o.y = v00.y * gx + v01.y * fx;
        o.z = v00.z * gx + v01.z * fx;
        o.w = v00.w * gx + v01.w * fx;
    } else if (needY) {
        // fx == 0: top = v00, bot = v10 exactly
        o.x = v00.x * gy + v10.x * fy;
        o.y = v00.y * gy + v10.y * fy;
        o.z = v00.z * gy + v10.z * fy;
        o.w = v00.w * gy + v10.w * fy;
    } else {
        // fx == fy == 0: out = v00 exactly
        o = v00;
    }

    float4* dst = reinterpret_cast<float4*>(out + (size_t)pid * CH) + lane;
    __stcs(dst, o);
}

extern "C" void kernel_launch(void* const* d_in, const int* in_sizes, int n_in,
                              void* d_out, int out_size)
{
    const float* img  = (const float*)d_in[0];
    const float* rois = (const float*)d_in[1];
    float* out = (float*)d_out;

    const int totalPixels = NUM_ROIS * POOL * POOL;  // 25088
    const int threads = 256;                         // 8 warps = 8 pixels/block
    const int warpsPerBlock = threads / 32;
    const int blocks = (totalPixels + warpsPerBlock - 1) / warpsPerBlock;

    roi_pool_kernel<<<blocks, threads>>>(img, rois, out);
}